// round 1
// baseline (speedup 1.0000x reference)
#include <cuda_runtime.h>

// ---------------------------------------------------------------------------
// RecurrentGraphNeuralNet:
//   agg[d]  = sum_{e: dst[e]=d} x[src[e]]        (scatter-add, fp32 atomics)
//   mean    = agg / max(deg,1)
//   x_new   = relu([mean|u] @ [W;B] + b)          (fused K=128 GEMM)
//   y       = x_new @ Wp + bp
//   out     = concat(x_new [N*64], y [N*32])
// ---------------------------------------------------------------------------

#define MAXN 100000
#define HH 64

__device__ float g_agg[(long long)MAXN * HH];
__device__ float g_deg[MAXN];
__device__ int   g_is64;

// ---------------------------------------------------------------------------
__global__ void detect_idx_kernel(const void* ei, int E, int N) {
    if (blockIdx.x == 0 && threadIdx.x == 0) {
        const long long* p = (const long long*)ei;
        int is64 = 1;
        #pragma unroll
        for (int i = 0; i < 8; i++) {
            long long v = p[i];
            if (v < 0 || v >= (long long)N) { is64 = 0; break; }
        }
        g_is64 = is64;
    }
}

// ---------------------------------------------------------------------------
__global__ void init_kernel(long long nagg4, int n) {
    long long i = (long long)blockIdx.x * blockDim.x + threadIdx.x;
    if (i < nagg4) {
        *reinterpret_cast<float4*>(g_agg + i * 4) = make_float4(0.f, 0.f, 0.f, 0.f);
    }
    if (i < n) g_deg[i] = 0.f;
}

// ---------------------------------------------------------------------------
// One thread per (edge, 4-feature chunk): 16 threads/edge, float4 gather,
// 4 scalar fp32 atomicAdds (compile to RED.ADD, no return).
__global__ __launch_bounds__(256) void scatter_kernel(
    const float* __restrict__ x, const void* __restrict__ ei_raw, int E)
{
    long long idx = (long long)blockIdx.x * blockDim.x + threadIdx.x;
    long long total = (long long)E * 16;
    if (idx >= total) return;

    int e  = (int)(idx >> 4);
    int f4 = ((int)idx & 15) * 4;

    int s, d;
    if (g_is64) {
        const long long* ei = (const long long*)ei_raw;
        s = (int)ei[e];
        d = (int)ei[(long long)E + e];
    } else {
        const int* ei = (const int*)ei_raw;
        s = ei[e];
        d = ei[E + e];
    }

    float4 v = *reinterpret_cast<const float4*>(x + (long long)s * 64 + f4);
    float* dst = g_agg + (long long)d * 64 + f4;
    atomicAdd(dst + 0, v.x);
    atomicAdd(dst + 1, v.y);
    atomicAdd(dst + 2, v.z);
    atomicAdd(dst + 3, v.w);

    if ((idx & 15) == 0) atomicAdd(&g_deg[d], 1.0f);
}

// ---------------------------------------------------------------------------
// Fused update: 64 nodes per block, 256 threads.
// Shared layout (floats):
//   ms  [64][130] : concat(mean, u) per node, padded stride   8320
//   wb  [128][64] : concat(W, B)                              8192
//   wps [64][32]  : Wp                                        2048
//   xn  [64][68]  : x_new staging, padded stride              4352
//   invd[64], bs[64], bps[32]                                  160
// total 23072 floats = 92288 B  (dynamic smem, 2 blocks/SM)
__global__ __launch_bounds__(256, 2) void update_kernel(
    const float* __restrict__ u, const float* __restrict__ W,
    const float* __restrict__ B, const float* __restrict__ b,
    const float* __restrict__ Wp, const float* __restrict__ bp,
    float* __restrict__ out, int N)
{
    extern __shared__ float sm[];
    float* ms   = sm;                    // 8320
    float* wb   = ms + 64 * 130;         // 8192
    float* wps  = wb + 128 * 64;         // 2048
    float* xn   = wps + 64 * 32;         // 4352
    float* invd = xn + 64 * 68;          // 64
    float* bs   = invd + 64;             // 64
    float* bps  = bs + 64;               // 32

    const int t = threadIdx.x;
    const int base = blockIdx.x * 64;

    // stage weights
    for (int i = t; i < 64 * 64; i += 256) {
        wb[i]        = W[i];
        wb[4096 + i] = B[i];
    }
    for (int i = t; i < 64 * 32; i += 256) wps[i] = Wp[i];
    if (t < 64) bs[t]  = b[t];
    if (t < 32) bps[t] = bp[t];
    if (t < 64) {
        int gn = base + t;
        float dg = (gn < N) ? g_deg[gn] : 1.0f;
        invd[t] = 1.0f / fmaxf(dg, 1.0f);
    }
    __syncthreads();

    // stage [mean | u] rows
    for (int i = t; i < 64 * 64; i += 256) {
        int node = i >> 6, k = i & 63;
        int gn = base + node;
        float mv = 0.f, uv = 0.f;
        if (gn < N) {
            mv = g_agg[(long long)gn * 64 + k] * invd[node];
            uv = u[(long long)gn * 64 + k];
        }
        ms[node * 130 + k]      = mv;
        ms[node * 130 + 64 + k] = uv;
    }
    __syncthreads();

    const int tx = t & 15;   // h-group : h = tx*4
    const int ty = t >> 4;   // node-group: nodes ty*4 .. ty*4+3
    const int h0 = tx * 4;
    const int n0 = ty * 4;

    const float* m0 = ms + (n0 + 0) * 130;
    const float* m1 = ms + (n0 + 1) * 130;
    const float* m2 = ms + (n0 + 2) * 130;
    const float* m3 = ms + (n0 + 3) * 130;

    float acc[4][4];
    #pragma unroll
    for (int i = 0; i < 4; i++)
        #pragma unroll
        for (int j = 0; j < 4; j++) acc[i][j] = 0.f;

    #pragma unroll 4
    for (int k = 0; k < 128; k++) {
        float4 wv = *reinterpret_cast<const float4*>(wb + k * 64 + h0);
        float a0 = m0[k], a1 = m1[k], a2 = m2[k], a3 = m3[k];
        acc[0][0] = fmaf(a0, wv.x, acc[0][0]);
        acc[0][1] = fmaf(a0, wv.y, acc[0][1]);
        acc[0][2] = fmaf(a0, wv.z, acc[0][2]);
        acc[0][3] = fmaf(a0, wv.w, acc[0][3]);
        acc[1][0] = fmaf(a1, wv.x, acc[1][0]);
        acc[1][1] = fmaf(a1, wv.y, acc[1][1]);
        acc[1][2] = fmaf(a1, wv.z, acc[1][2]);
        acc[1][3] = fmaf(a1, wv.w, acc[1][3]);
        acc[2][0] = fmaf(a2, wv.x, acc[2][0]);
        acc[2][1] = fmaf(a2, wv.y, acc[2][1]);
        acc[2][2] = fmaf(a2, wv.z, acc[2][2]);
        acc[2][3] = fmaf(a2, wv.w, acc[2][3]);
        acc[3][0] = fmaf(a3, wv.x, acc[3][0]);
        acc[3][1] = fmaf(a3, wv.y, acc[3][1]);
        acc[3][2] = fmaf(a3, wv.z, acc[3][2]);
        acc[3][3] = fmaf(a3, wv.w, acc[3][3]);
    }

    // bias + relu, store x_new to out and to shared staging for y
    #pragma unroll
    for (int i = 0; i < 4; i++) {
        float4 v;
        v.x = fmaxf(acc[i][0] + bs[h0 + 0], 0.f);
        v.y = fmaxf(acc[i][1] + bs[h0 + 1], 0.f);
        v.z = fmaxf(acc[i][2] + bs[h0 + 2], 0.f);
        v.w = fmaxf(acc[i][3] + bs[h0 + 3], 0.f);
        int node = n0 + i;
        *reinterpret_cast<float4*>(xn + node * 68 + h0) = v;
        int gn = base + node;
        if (gn < N)
            *reinterpret_cast<float4*>(out + (long long)gn * 64 + h0) = v;
    }
    __syncthreads();

    // prediction head: y = x_new @ Wp + bp ; thread -> 4 nodes x 2 p-cols
    const int p0 = tx * 2;
    float y0[4] = {0.f, 0.f, 0.f, 0.f};
    float y1[4] = {0.f, 0.f, 0.f, 0.f};
    #pragma unroll 4
    for (int k = 0; k < 64; k++) {
        float2 wpv = *reinterpret_cast<const float2*>(wps + k * 32 + p0);
        #pragma unroll
        for (int i = 0; i < 4; i++) {
            float a = xn[(n0 + i) * 68 + k];
            y0[i] = fmaf(a, wpv.x, y0[i]);
            y1[i] = fmaf(a, wpv.y, y1[i]);
        }
    }
    float* outy = out + (long long)N * 64;
    #pragma unroll
    for (int i = 0; i < 4; i++) {
        int gn = base + n0 + i;
        if (gn < N) {
            float2 r;
            r.x = y0[i] + bps[p0 + 0];
            r.y = y1[i] + bps[p0 + 1];
            *reinterpret_cast<float2*>(outy + (long long)gn * 32 + p0) = r;
        }
    }
}

// ---------------------------------------------------------------------------
extern "C" void kernel_launch(void* const* d_in, const int* in_sizes, int n_in,
                              void* d_out, int out_size)
{
    const float* x  = (const float*)d_in[0];
    const float* u  = (const float*)d_in[1];
    const void*  ei = d_in[2];
    const float* W  = (const float*)d_in[3];
    const float* B  = (const float*)d_in[4];
    const float* b  = (const float*)d_in[5];
    const float* Wp = (const float*)d_in[6];
    const float* bp = (const float*)d_in[7];
    float* out = (float*)d_out;

    int N = in_sizes[0] / 64;
    int E = in_sizes[2] / 2;

    const int smem_bytes = 23072 * 4;  // 92288
    cudaFuncSetAttribute(update_kernel,
                         cudaFuncAttributeMaxDynamicSharedMemorySize, smem_bytes);

    // 1) detect edge-index dtype (int64 requested by reference, but JAX
    //    without x64 emits int32 — decide on-device)
    detect_idx_kernel<<<1, 32>>>(ei, E, N);

    // 2) zero scratch
    long long nagg4 = ((long long)N * 64) / 4;
    int init_blocks = (int)((nagg4 + 255) / 256);
    init_kernel<<<init_blocks, 256>>>(nagg4, N);

    // 3) edge scatter-add (16 threads per edge)
    long long sc_threads = (long long)E * 16;
    int sc_blocks = (int)((sc_threads + 255) / 256);
    scatter_kernel<<<sc_blocks, 256>>>(x, ei, E);

    // 4) fused mean/GEMM/relu/prediction
    int up_blocks = (N + 63) / 64;
    update_kernel<<<up_blocks, 256, smem_bytes>>>(u, W, B, b, Wp, bp, out, N);
}

// round 3
// speedup vs baseline: 1.6482x; 1.6482x over previous
#include <cuda_runtime.h>

// ---------------------------------------------------------------------------
// RecurrentGraphNeuralNet:
//   agg[d]  = sum_{e: dst[e]=d} x[src[e]]        (scatter via red.global.v4)
//   mean    = agg / max(deg,1)
//   x_new   = relu(mean@W + u@B + b)             (two-phase K=64+64 GEMM)
//   y       = x_new @ Wp + bp
//   out     = concat(x_new [N*64], y [N*32])
// ---------------------------------------------------------------------------

#define MAXN 100000
#define HH 64
#define US 65          // a_buf row stride (floats), conflict-free

__device__ float g_agg[(long long)MAXN * HH];
__device__ float g_deg[MAXN];
__device__ int   g_is64;

// ---------------------------------------------------------------------------
__global__ void detect_idx_kernel(const void* ei, int E, int N) {
    if (blockIdx.x == 0 && threadIdx.x == 0) {
        const long long* p = (const long long*)ei;
        int is64 = 1;
        #pragma unroll
        for (int i = 0; i < 8; i++) {
            long long v = p[i];
            if (v < 0 || v >= (long long)N) { is64 = 0; break; }
        }
        g_is64 = is64;
    }
}

// ---------------------------------------------------------------------------
__global__ void init_kernel(long long nagg4, int n) {
    long long i = (long long)blockIdx.x * blockDim.x + threadIdx.x;
    if (i < nagg4) {
        *reinterpret_cast<float4*>(g_agg + i * 4) = make_float4(0.f, 0.f, 0.f, 0.f);
    }
    if (i < n) g_deg[i] = 0.f;
}

// ---------------------------------------------------------------------------
// 16 threads per edge: float4 gather + ONE vectorized red.global.add.v4.f32
// (4x fewer atomic instructions than scalar RED.ADD).
__global__ __launch_bounds__(256) void scatter_kernel(
    const float* __restrict__ x, const void* __restrict__ ei_raw, int E)
{
    long long idx = (long long)blockIdx.x * blockDim.x + threadIdx.x;
    long long total = (long long)E * 16;
    if (idx >= total) return;

    const int is64 = g_is64;   // uniform
    int e  = (int)(idx >> 4);
    int f4 = ((int)idx & 15) * 4;

    int s, d;
    if (is64) {
        const long long* ei = (const long long*)ei_raw;
        s = (int)ei[e];
        d = (int)ei[(long long)E + e];
    } else {
        const int* ei = (const int*)ei_raw;
        s = ei[e];
        d = ei[E + e];
    }

    float4 v = *reinterpret_cast<const float4*>(x + (long long)s * 64 + f4);
    float* dst = g_agg + (long long)d * 64 + f4;
    asm volatile("red.global.add.v4.f32 [%0], {%1, %2, %3, %4};"
                 :: "l"(dst), "f"(v.x), "f"(v.y), "f"(v.z), "f"(v.w)
                 : "memory");

    if ((idx & 15) == 0) atomicAdd(&g_deg[d], 1.0f);
}

// ---------------------------------------------------------------------------
// Fused update: 128 nodes per block, 256 threads, smem 50.6KB -> 4 blocks/SM.
// K is processed in two phases (mean@W, then u@B) accumulating into the same
// registers, so only one 128x64 A tile + one 64x64 W tile live at a time.
// Thread tile: 4 nodes x 8 h  (tx = t&7 -> h0 = tx*8 ; ty = t>>3 -> n0 = ty*4).
// Shared (floats): a_buf 128*65 = 8320 ; w_buf 4096 ; invd 128 ; bs 64 ; bps 32
//   total 12640 floats = 50560 B.
__global__ __launch_bounds__(256, 4) void update_kernel(
    const float* __restrict__ u, const float* __restrict__ W,
    const float* __restrict__ B, const float* __restrict__ b,
    const float* __restrict__ Wp, const float* __restrict__ bp,
    float* __restrict__ out, int N)
{
    extern __shared__ float sm[];
    float* a_buf = sm;                 // 128 * 65
    float* w_buf = a_buf + 128 * US;   // 64 * 64
    float* invd  = w_buf + 4096;       // 128
    float* bs    = invd + 128;         // 64
    float* bps   = bs + 64;            // 32

    const int t = threadIdx.x;
    const int base = blockIdx.x * 128;

    // --- prologue: invd, bias, W tile ---
    if (t < 128) {
        int gn = base + t;
        float dg = (gn < N) ? g_deg[gn] : 1.0f;
        invd[t] = 1.0f / fmaxf(dg, 1.0f);
    }
    if (t < 64) bs[t] = b[t];
    for (int i = t; i < 4096; i += 256) w_buf[i] = W[i];
    __syncthreads();

    // --- stage mean (scaled agg) ---
    for (int i = t; i < 128 * 64; i += 256) {
        int node = i >> 6, k = i & 63;
        int gn = base + node;
        a_buf[node * US + k] =
            (gn < N) ? g_agg[(long long)gn * 64 + k] * invd[node] : 0.f;
    }
    __syncthreads();

    const int tx = t & 7;      // h0 = tx*8
    const int ty = t >> 3;     // n0 = ty*4
    const int h0 = tx * 8;
    const int n0 = ty * 4;

    float acc[4][8];
    #pragma unroll
    for (int i = 0; i < 4; i++)
        #pragma unroll
        for (int j = 0; j < 8; j++) acc[i][j] = 0.f;

    // --- phase 0: acc += mean @ W ---
    #pragma unroll 4
    for (int k = 0; k < 64; k++) {
        float4 w0 = *reinterpret_cast<const float4*>(w_buf + k * 64 + h0);
        float4 w1 = *reinterpret_cast<const float4*>(w_buf + k * 64 + h0 + 4);
        #pragma unroll
        for (int i = 0; i < 4; i++) {
            float a = a_buf[(n0 + i) * US + k];
            acc[i][0] = fmaf(a, w0.x, acc[i][0]);
            acc[i][1] = fmaf(a, w0.y, acc[i][1]);
            acc[i][2] = fmaf(a, w0.z, acc[i][2]);
            acc[i][3] = fmaf(a, w0.w, acc[i][3]);
            acc[i][4] = fmaf(a, w1.x, acc[i][4]);
            acc[i][5] = fmaf(a, w1.y, acc[i][5]);
            acc[i][6] = fmaf(a, w1.z, acc[i][6]);
            acc[i][7] = fmaf(a, w1.w, acc[i][7]);
        }
    }
    __syncthreads();

    // --- swap tiles: B weights + u features ---
    for (int i = t; i < 4096; i += 256) w_buf[i] = B[i];
    for (int i = t; i < 128 * 64; i += 256) {
        int node = i >> 6, k = i & 63;
        int gn = base + node;
        a_buf[node * US + k] = (gn < N) ? u[(long long)gn * 64 + k] : 0.f;
    }
    __syncthreads();

    // --- phase 1: acc += u @ B ---
    #pragma unroll 4
    for (int k = 0; k < 64; k++) {
        float4 w0 = *reinterpret_cast<const float4*>(w_buf + k * 64 + h0);
        float4 w1 = *reinterpret_cast<const float4*>(w_buf + k * 64 + h0 + 4);
        #pragma unroll
        for (int i = 0; i < 4; i++) {
            float a = a_buf[(n0 + i) * US + k];
            acc[i][0] = fmaf(a, w0.x, acc[i][0]);
            acc[i][1] = fmaf(a, w0.y, acc[i][1]);
            acc[i][2] = fmaf(a, w0.z, acc[i][2]);
            acc[i][3] = fmaf(a, w0.w, acc[i][3]);
            acc[i][4] = fmaf(a, w1.x, acc[i][4]);
            acc[i][5] = fmaf(a, w1.y, acc[i][5]);
            acc[i][6] = fmaf(a, w1.z, acc[i][6]);
            acc[i][7] = fmaf(a, w1.w, acc[i][7]);
        }
    }

    // --- bias + relu ; write x_new to out ---
    #pragma unroll
    for (int i = 0; i < 4; i++) {
        #pragma unroll
        for (int j = 0; j < 8; j++)
            acc[i][j] = fmaxf(acc[i][j] + bs[h0 + j], 0.f);
        int gn = base + n0 + i;
        if (gn < N) {
            float4 v0 = make_float4(acc[i][0], acc[i][1], acc[i][2], acc[i][3]);
            float4 v1 = make_float4(acc[i][4], acc[i][5], acc[i][6], acc[i][7]);
            *reinterpret_cast<float4*>(out + (long long)gn * 64 + h0)     = v0;
            *reinterpret_cast<float4*>(out + (long long)gn * 64 + h0 + 4) = v1;
        }
    }
    __syncthreads();   // everyone done reading a_buf / w_buf

    // --- stage x_new into a_buf ; Wp into w_buf ---
    #pragma unroll
    for (int i = 0; i < 4; i++)
        #pragma unroll
        for (int j = 0; j < 8; j++)
            a_buf[(n0 + i) * US + h0 + j] = acc[i][j];
    for (int i = t; i < 64 * 32; i += 256) w_buf[i] = Wp[i];
    if (t < 32) bps[t] = bp[t];
    __syncthreads();

    // --- head: y = x_new @ Wp + bp ; thread tile 4 nodes x 4 p ---
    const int p0 = tx * 4;
    float yacc[4][4];
    #pragma unroll
    for (int i = 0; i < 4; i++)
        #pragma unroll
        for (int j = 0; j < 4; j++) yacc[i][j] = 0.f;

    #pragma unroll 4
    for (int k = 0; k < 64; k++) {
        float4 wp = *reinterpret_cast<const float4*>(w_buf + k * 32 + p0);
        #pragma unroll
        for (int i = 0; i < 4; i++) {
            float a = a_buf[(n0 + i) * US + k];
            yacc[i][0] = fmaf(a, wp.x, yacc[i][0]);
            yacc[i][1] = fmaf(a, wp.y, yacc[i][1]);
            yacc[i][2] = fmaf(a, wp.z, yacc[i][2]);
            yacc[i][3] = fmaf(a, wp.w, yacc[i][3]);
        }
    }

    float* outy = out + (long long)N * 64;
    #pragma unroll
    for (int i = 0; i < 4; i++) {
        int gn = base + n0 + i;
        if (gn < N) {
            float4 r;
            r.x = yacc[i][0] + bps[p0 + 0];
            r.y = yacc[i][1] + bps[p0 + 1];
            r.z = yacc[i][2] + bps[p0 + 2];
            r.w = yacc[i][3] + bps[p0 + 3];
            *reinterpret_cast<float4*>(outy + (long long)gn * 32 + p0) = r;
        }
    }
}

// ---------------------------------------------------------------------------
extern "C" void kernel_launch(void* const* d_in, const int* in_sizes, int n_in,
                              void* d_out, int out_size)
{
    const float* x  = (const float*)d_in[0];
    const float* u  = (const float*)d_in[1];
    const void*  ei = d_in[2];
    const float* W  = (const float*)d_in[3];
    const float* B  = (const float*)d_in[4];
    const float* b  = (const float*)d_in[5];
    const float* Wp = (const float*)d_in[6];
    const float* bp = (const float*)d_in[7];
    float* out = (float*)d_out;

    int N = in_sizes[0] / 64;
    int E = in_sizes[2] / 2;

    const int smem_bytes = 12640 * 4;  // 50560
    cudaFuncSetAttribute(update_kernel,
                         cudaFuncAttributeMaxDynamicSharedMemorySize, smem_bytes);

    detect_idx_kernel<<<1, 32>>>(ei, E, N);

    long long nagg4 = ((long long)N * 64) / 4;
    int init_blocks = (int)((nagg4 + 255) / 256);
    init_kernel<<<init_blocks, 256>>>(nagg4, N);

    long long sc_threads = (long long)E * 16;
    int sc_blocks = (int)((sc_threads + 255) / 256);
    scatter_kernel<<<sc_blocks, 256>>>(x, ei, E);

    int up_blocks = (N + 127) / 128;
    update_kernel<<<up_blocks, 256, smem_bytes>>>(u, W, B, b, Wp, bp, out, N);
}

// round 4
// speedup vs baseline: 1.8460x; 1.1200x over previous
#include <cuda_runtime.h>

// ---------------------------------------------------------------------------
// RecurrentGraphNeuralNet:
//   agg[d]  = sum_{e: dst[e]=d} x[src[e]]        (scatter via red.global.v4)
//   mean    = agg / max(deg,1)
//   x_new   = relu(mean@W + u@B + b)             (two-phase K=64+64 GEMM)
//   y       = x_new @ Wp + bp
//   out     = concat(x_new [N*64], y [N*32])
//
// Update kernel v3: A tile TRANSPOSED in smem (aT[k][node], stride 132) so one
// LDS.128 feeds 4 nodes; W columns split into {tx*4, 32+tx*4} so each W
// LDS.128 phase covers 128 contiguous bytes (conflict-free).
// Inner loop: 3 LDS.128 per 32 FMA (was 6 LDS, 2-way conflicted).
// ---------------------------------------------------------------------------

#define MAXN 100000
#define AS 132            // aT row stride (floats): 132 mod 32 = 4, 16B aligned

__device__ float g_agg[(long long)MAXN * 64];
__device__ float g_deg[MAXN];
__device__ int   g_is64;

// ---------------------------------------------------------------------------
__global__ void detect_idx_kernel(const void* ei, int E, int N) {
    if (blockIdx.x == 0 && threadIdx.x == 0) {
        const long long* p = (const long long*)ei;
        int is64 = 1;
        #pragma unroll
        for (int i = 0; i < 8; i++) {
            long long v = p[i];
            if (v < 0 || v >= (long long)N) { is64 = 0; break; }
        }
        g_is64 = is64;
    }
}

// ---------------------------------------------------------------------------
__global__ void init_kernel(long long nagg4, int n) {
    long long i = (long long)blockIdx.x * blockDim.x + threadIdx.x;
    if (i < nagg4) {
        *reinterpret_cast<float4*>(g_agg + i * 4) = make_float4(0.f, 0.f, 0.f, 0.f);
    }
    if (i < n) g_deg[i] = 0.f;
}

// ---------------------------------------------------------------------------
// 16 threads per edge: float4 gather + one red.global.add.v4.f32.
__global__ __launch_bounds__(256) void scatter_kernel(
    const float* __restrict__ x, const void* __restrict__ ei_raw, int E)
{
    long long idx = (long long)blockIdx.x * blockDim.x + threadIdx.x;
    long long total = (long long)E * 16;
    if (idx >= total) return;

    const int is64 = g_is64;
    int e  = (int)(idx >> 4);
    int f4 = ((int)idx & 15) * 4;

    int s, d;
    if (is64) {
        const long long* ei = (const long long*)ei_raw;
        s = (int)ei[e];
        d = (int)ei[(long long)E + e];
    } else {
        const int* ei = (const int*)ei_raw;
        s = ei[e];
        d = ei[E + e];
    }

    float4 v = *reinterpret_cast<const float4*>(x + (long long)s * 64 + f4);
    float* dst = g_agg + (long long)d * 64 + f4;
    asm volatile("red.global.add.v4.f32 [%0], {%1, %2, %3, %4};"
                 :: "l"(dst), "f"(v.x), "f"(v.y), "f"(v.z), "f"(v.w)
                 : "memory");

    if ((idx & 15) == 0) atomicAdd(&g_deg[d], 1.0f);
}

// ---------------------------------------------------------------------------
// 128 nodes / block, 256 threads, 4 blocks/SM.
// Shared (floats): aT 64*132=8448 ; w_buf 4096 ; invd 128 ; bs 64 ; bps 32
//   = 12768 floats = 51072 B  (x4 blocks = 204 KB/SM)
// Thread tile: tx = t&7 (columns tx*4 and 32+tx*4), ty = t>>3 (nodes ty*4..+3)
// acc layout acc[c][i]: c = column-within-group, i = node  -> row-wise STS.128
__global__ __launch_bounds__(256, 4) void update_kernel(
    const float* __restrict__ u, const float* __restrict__ W,
    const float* __restrict__ B, const float* __restrict__ b,
    const float* __restrict__ Wp, const float* __restrict__ bp,
    float* __restrict__ out, int N)
{
    extern __shared__ float sm[];
    float* aT    = sm;                 // 64 * 132
    float* w_buf = aT + 64 * AS;       // 64 * 64
    float* invd  = w_buf + 4096;       // 128
    float* bs    = invd + 128;         // 64
    float* bps   = bs + 64;            // 32

    const int t = threadIdx.x;
    const int base = blockIdx.x * 128;

    // --- prologue ---
    if (t < 128) {
        int gn = base + t;
        float dg = (gn < N) ? g_deg[gn] : 1.0f;
        invd[t] = 1.0f / fmaxf(dg, 1.0f);
    }
    if (t < 64) bs[t] = b[t];
    if (t >= 64 && t < 96) bps[t - 64] = bp[t - 64];
    for (int i = t; i < 4096; i += 256) w_buf[i] = W[i];
    __syncthreads();

    // --- stage mean transposed: aT[k][node] ---
    for (int i = t; i < 128 * 64; i += 256) {
        int node = i >> 6, k = i & 63;               // gmem coalesced
        int gn = base + node;
        aT[k * AS + node] =
            (gn < N) ? g_agg[(long long)gn * 64 + k] * invd[node] : 0.f;
    }
    __syncthreads();

    const int tx = t & 7;
    const int ty = t >> 3;
    const int hA = tx * 4;         // columns hA..hA+3
    const int hB = 32 + tx * 4;    // columns hB..hB+3
    const int n0 = ty * 4;         // nodes  n0..n0+3

    float accA[4][4], accB[4][4];  // [c][i]
    #pragma unroll
    for (int c = 0; c < 4; c++)
        #pragma unroll
        for (int i = 0; i < 4; i++) { accA[c][i] = 0.f; accB[c][i] = 0.f; }

    // --- phase 0: += mean @ W ---
    #pragma unroll 8
    for (int k = 0; k < 64; k++) {
        float4 av = *reinterpret_cast<const float4*>(aT + k * AS + n0);
        float4 w0 = *reinterpret_cast<const float4*>(w_buf + k * 64 + hA);
        float4 w1 = *reinterpret_cast<const float4*>(w_buf + k * 64 + hB);
        const float a[4] = {av.x, av.y, av.z, av.w};
        #pragma unroll
        for (int i = 0; i < 4; i++) {
            accA[0][i] = fmaf(a[i], w0.x, accA[0][i]);
            accA[1][i] = fmaf(a[i], w0.y, accA[1][i]);
            accA[2][i] = fmaf(a[i], w0.z, accA[2][i]);
            accA[3][i] = fmaf(a[i], w0.w, accA[3][i]);
            accB[0][i] = fmaf(a[i], w1.x, accB[0][i]);
            accB[1][i] = fmaf(a[i], w1.y, accB[1][i]);
            accB[2][i] = fmaf(a[i], w1.z, accB[2][i]);
            accB[3][i] = fmaf(a[i], w1.w, accB[3][i]);
        }
    }
    __syncthreads();

    // --- swap tiles: B weights + u (transposed) ---
    for (int i = t; i < 4096; i += 256) w_buf[i] = B[i];
    for (int i = t; i < 128 * 64; i += 256) {
        int node = i >> 6, k = i & 63;
        int gn = base + node;
        aT[k * AS + node] = (gn < N) ? u[(long long)gn * 64 + k] : 0.f;
    }
    __syncthreads();

    // --- phase 1: += u @ B ---
    #pragma unroll 8
    for (int k = 0; k < 64; k++) {
        float4 av = *reinterpret_cast<const float4*>(aT + k * AS + n0);
        float4 w0 = *reinterpret_cast<const float4*>(w_buf + k * 64 + hA);
        float4 w1 = *reinterpret_cast<const float4*>(w_buf + k * 64 + hB);
        const float a[4] = {av.x, av.y, av.z, av.w};
        #pragma unroll
        for (int i = 0; i < 4; i++) {
            accA[0][i] = fmaf(a[i], w0.x, accA[0][i]);
            accA[1][i] = fmaf(a[i], w0.y, accA[1][i]);
            accA[2][i] = fmaf(a[i], w0.z, accA[2][i]);
            accA[3][i] = fmaf(a[i], w0.w, accA[3][i]);
            accB[0][i] = fmaf(a[i], w1.x, accB[0][i]);
            accB[1][i] = fmaf(a[i], w1.y, accB[1][i]);
            accB[2][i] = fmaf(a[i], w1.z, accB[2][i]);
            accB[3][i] = fmaf(a[i], w1.w, accB[3][i]);
        }
    }

    // --- bias + relu ---
    #pragma unroll
    for (int c = 0; c < 4; c++) {
        float bA = bs[hA + c], bB = bs[hB + c];
        #pragma unroll
        for (int i = 0; i < 4; i++) {
            accA[c][i] = fmaxf(accA[c][i] + bA, 0.f);
            accB[c][i] = fmaxf(accB[c][i] + bB, 0.f);
        }
    }

    // --- write x_new to out (float4 across h per node) ---
    #pragma unroll
    for (int i = 0; i < 4; i++) {
        int gn = base + n0 + i;
        if (gn < N) {
            float4 vA = make_float4(accA[0][i], accA[1][i], accA[2][i], accA[3][i]);
            float4 vB = make_float4(accB[0][i], accB[1][i], accB[2][i], accB[3][i]);
            *reinterpret_cast<float4*>(out + (long long)gn * 64 + hA) = vA;
            *reinterpret_cast<float4*>(out + (long long)gn * 64 + hB) = vB;
        }
    }
    __syncthreads();   // phase-1 reads of aT / w_buf done

    // --- restage: x_new transposed into aT (row-wise STS.128), Wp into w_buf
    #pragma unroll
    for (int c = 0; c < 4; c++) {
        *reinterpret_cast<float4*>(aT + (hA + c) * AS + n0) =
            make_float4(accA[c][0], accA[c][1], accA[c][2], accA[c][3]);
        *reinterpret_cast<float4*>(aT + (hB + c) * AS + n0) =
            make_float4(accB[c][0], accB[c][1], accB[c][2], accB[c][3]);
    }
    for (int i = t; i < 64 * 32; i += 256) w_buf[i] = Wp[i];
    __syncthreads();

    // --- head: y = x_new @ Wp + bp ; tile 4 nodes x 4 p ---
    const int p0 = tx * 4;
    float yacc[4][4];   // [c][i]
    #pragma unroll
    for (int c = 0; c < 4; c++)
        #pragma unroll
        for (int i = 0; i < 4; i++) yacc[c][i] = 0.f;

    #pragma unroll 8
    for (int k = 0; k < 64; k++) {
        float4 av = *reinterpret_cast<const float4*>(aT + k * AS + n0);
        float4 wp = *reinterpret_cast<const float4*>(w_buf + k * 32 + p0);
        const float a[4] = {av.x, av.y, av.z, av.w};
        #pragma unroll
        for (int i = 0; i < 4; i++) {
            yacc[0][i] = fmaf(a[i], wp.x, yacc[0][i]);
            yacc[1][i] = fmaf(a[i], wp.y, yacc[1][i]);
            yacc[2][i] = fmaf(a[i], wp.z, yacc[2][i]);
            yacc[3][i] = fmaf(a[i], wp.w, yacc[3][i]);
        }
    }

    float* outy = out + (long long)N * 64;
    #pragma unroll
    for (int i = 0; i < 4; i++) {
        int gn = base + n0 + i;
        if (gn < N) {
            float4 r;
            r.x = yacc[0][i] + bps[p0 + 0];
            r.y = yacc[1][i] + bps[p0 + 1];
            r.z = yacc[2][i] + bps[p0 + 2];
            r.w = yacc[3][i] + bps[p0 + 3];
            *reinterpret_cast<float4*>(outy + (long long)gn * 32 + p0) = r;
        }
    }
}

// ---------------------------------------------------------------------------
extern "C" void kernel_launch(void* const* d_in, const int* in_sizes, int n_in,
                              void* d_out, int out_size)
{
    const float* x  = (const float*)d_in[0];
    const float* u  = (const float*)d_in[1];
    const void*  ei = d_in[2];
    const float* W  = (const float*)d_in[3];
    const float* B  = (const float*)d_in[4];
    const float* b  = (const float*)d_in[5];
    const float* Wp = (const float*)d_in[6];
    const float* bp = (const float*)d_in[7];
    float* out = (float*)d_out;

    int N = in_sizes[0] / 64;
    int E = in_sizes[2] / 2;

    const int smem_bytes = 12768 * 4;  // 51072
    cudaFuncSetAttribute(update_kernel,
                         cudaFuncAttributeMaxDynamicSharedMemorySize, smem_bytes);

    detect_idx_kernel<<<1, 32>>>(ei, E, N);

    long long nagg4 = ((long long)N * 64) / 4;
    int init_blocks = (int)((nagg4 + 255) / 256);
    init_kernel<<<init_blocks, 256>>>(nagg4, N);

    long long sc_threads = (long long)E * 16;
    int sc_blocks = (int)((sc_threads + 255) / 256);
    scatter_kernel<<<sc_blocks, 256>>>(x, ei, E);

    int up_blocks = (N + 127) / 128;
    update_kernel<<<up_blocks, 256, smem_bytes>>>(u, W, B, b, Wp, bp, out, N);
}

// round 5
// speedup vs baseline: 1.8861x; 1.0217x over previous
#include <cuda_runtime.h>

// ---------------------------------------------------------------------------
// RecurrentGraphNeuralNet:
//   agg[d]  = sum_{e: dst[e]=d} x[src[e]]        (scatter via red.global.v4)
//   mean    = agg / max(deg,1)
//   x_new   = relu(mean@W + u@B + b)             (two-phase K=64+64 GEMM)
//   y       = x_new @ Wp + bp
//   out     = concat(x_new [N*64], y [N*32])
//
// Update v4: 256 nodes/block, 8x8 thread tile -> 64B smem per 64 FMA
// (1.0 B/FMA), all LDS.128 conflict-free. FMA-pipe-bound by design.
// ---------------------------------------------------------------------------

#define MAXN 100000
#define AS 260            // aT row stride (floats): 16B-aligned float4 rows

__device__ float g_agg[(long long)MAXN * 64];
__device__ float g_deg[MAXN];
__device__ int   g_is64;

// ---------------------------------------------------------------------------
__global__ void detect_idx_kernel(const void* ei, int E, int N) {
    if (blockIdx.x == 0 && threadIdx.x == 0) {
        const long long* p = (const long long*)ei;
        int is64 = 1;
        #pragma unroll
        for (int i = 0; i < 8; i++) {
            long long v = p[i];
            if (v < 0 || v >= (long long)N) { is64 = 0; break; }
        }
        g_is64 = is64;
    }
}

// ---------------------------------------------------------------------------
__global__ void init_kernel(long long nagg4, int n) {
    long long i = (long long)blockIdx.x * blockDim.x + threadIdx.x;
    if (i < nagg4) {
        *reinterpret_cast<float4*>(g_agg + i * 4) = make_float4(0.f, 0.f, 0.f, 0.f);
    }
    if (i < n) g_deg[i] = 0.f;
}

// ---------------------------------------------------------------------------
// 16 threads per edge: float4 gather + one red.global.add.v4.f32.
__global__ __launch_bounds__(256) void scatter_kernel(
    const float* __restrict__ x, const void* __restrict__ ei_raw, int E)
{
    long long idx = (long long)blockIdx.x * blockDim.x + threadIdx.x;
    long long total = (long long)E * 16;
    if (idx >= total) return;

    const int is64 = g_is64;
    int e  = (int)(idx >> 4);
    int f4 = ((int)idx & 15) * 4;

    int s, d;
    if (is64) {
        const long long* ei = (const long long*)ei_raw;
        s = (int)ei[e];
        d = (int)ei[(long long)E + e];
    } else {
        const int* ei = (const int*)ei_raw;
        s = ei[e];
        d = ei[E + e];
    }

    float4 v = *reinterpret_cast<const float4*>(x + (long long)s * 64 + f4);
    float* dst = g_agg + (long long)d * 64 + f4;
    asm volatile("red.global.add.v4.f32 [%0], {%1, %2, %3, %4};"
                 :: "l"(dst), "f"(v.x), "f"(v.y), "f"(v.z), "f"(v.w)
                 : "memory");

    if ((idx & 15) == 0) atomicAdd(&g_deg[d], 1.0f);
}

// ---------------------------------------------------------------------------
// 256 nodes / block, 256 threads, 2 blocks/SM.
// Shared (floats): aT 64*260=16640 ; w_buf 4096 ; invd 256 ; bs 64 ; bps 32
//   = 21088 floats = 84352 B.
// Thread tile: tx = t&7 -> cols {tx*4..+3, 32+tx*4..+3}; ty = t>>3 -> nodes ty*8..+7.
__global__ __launch_bounds__(256, 2) void update_kernel(
    const float* __restrict__ u, const float* __restrict__ W,
    const float* __restrict__ B, const float* __restrict__ b,
    const float* __restrict__ Wp, const float* __restrict__ bp,
    float* __restrict__ out, int N)
{
    extern __shared__ float sm[];
    float* aT    = sm;                 // 64 * 260
    float* w_buf = aT + 64 * AS;       // 64 * 64
    float* invd  = w_buf + 4096;       // 256
    float* bs    = invd + 256;         // 64
    float* bps   = bs + 64;            // 32

    const int t = threadIdx.x;
    const int base = blockIdx.x * 256;

    // --- prologue ---
    {
        int gn = base + t;
        float dg = (gn < N) ? g_deg[gn] : 1.0f;
        invd[t] = 1.0f / fmaxf(dg, 1.0f);
    }
    if (t < 64) bs[t] = b[t];
    if (t >= 64 && t < 96) bps[t - 64] = bp[t - 64];
    for (int i = t; i < 4096; i += 256) w_buf[i] = W[i];
    __syncthreads();

    // --- stage mean transposed: aT[k][node] (float4 gmem reads) ---
    #pragma unroll
    for (int iter = 0; iter < 16; iter++) {
        int i = t + iter * 256;
        int node = i >> 4, k4 = (i & 15) * 4;
        int gn = base + node;
        float4 v = make_float4(0.f, 0.f, 0.f, 0.f);
        if (gn < N) {
            v = *reinterpret_cast<const float4*>(g_agg + (long long)gn * 64 + k4);
            float s = invd[node];
            v.x *= s; v.y *= s; v.z *= s; v.w *= s;
        }
        aT[(k4 + 0) * AS + node] = v.x;
        aT[(k4 + 1) * AS + node] = v.y;
        aT[(k4 + 2) * AS + node] = v.z;
        aT[(k4 + 3) * AS + node] = v.w;
    }
    __syncthreads();

    const int tx = t & 7;
    const int ty = t >> 3;
    const int hA = tx * 4;         // cols hA..hA+3
    const int hB = 32 + tx * 4;    // cols hB..hB+3
    const int n0 = ty * 8;         // nodes n0..n0+7

    float accA[4][8], accB[4][8];  // [col][node]
    #pragma unroll
    for (int c = 0; c < 4; c++)
        #pragma unroll
        for (int i = 0; i < 8; i++) { accA[c][i] = 0.f; accB[c][i] = 0.f; }

    // --- phase 0: += mean @ W ---
    #pragma unroll 4
    for (int k = 0; k < 64; k++) {
        float4 a0 = *reinterpret_cast<const float4*>(aT + k * AS + n0);
        float4 a1 = *reinterpret_cast<const float4*>(aT + k * AS + n0 + 4);
        float4 w0 = *reinterpret_cast<const float4*>(w_buf + k * 64 + hA);
        float4 w1 = *reinterpret_cast<const float4*>(w_buf + k * 64 + hB);
        const float a[8] = {a0.x, a0.y, a0.z, a0.w, a1.x, a1.y, a1.z, a1.w};
        #pragma unroll
        for (int i = 0; i < 8; i++) {
            accA[0][i] = fmaf(a[i], w0.x, accA[0][i]);
            accA[1][i] = fmaf(a[i], w0.y, accA[1][i]);
            accA[2][i] = fmaf(a[i], w0.z, accA[2][i]);
            accA[3][i] = fmaf(a[i], w0.w, accA[3][i]);
            accB[0][i] = fmaf(a[i], w1.x, accB[0][i]);
            accB[1][i] = fmaf(a[i], w1.y, accB[1][i]);
            accB[2][i] = fmaf(a[i], w1.z, accB[2][i]);
            accB[3][i] = fmaf(a[i], w1.w, accB[3][i]);
        }
    }
    __syncthreads();

    // --- swap tiles: B weights + u (transposed) ---
    for (int i = t; i < 4096; i += 256) w_buf[i] = B[i];
    #pragma unroll
    for (int iter = 0; iter < 16; iter++) {
        int i = t + iter * 256;
        int node = i >> 4, k4 = (i & 15) * 4;
        int gn = base + node;
        float4 v = make_float4(0.f, 0.f, 0.f, 0.f);
        if (gn < N)
            v = *reinterpret_cast<const float4*>(u + (long long)gn * 64 + k4);
        aT[(k4 + 0) * AS + node] = v.x;
        aT[(k4 + 1) * AS + node] = v.y;
        aT[(k4 + 2) * AS + node] = v.z;
        aT[(k4 + 3) * AS + node] = v.w;
    }
    __syncthreads();

    // --- phase 1: += u @ B ---
    #pragma unroll 4
    for (int k = 0; k < 64; k++) {
        float4 a0 = *reinterpret_cast<const float4*>(aT + k * AS + n0);
        float4 a1 = *reinterpret_cast<const float4*>(aT + k * AS + n0 + 4);
        float4 w0 = *reinterpret_cast<const float4*>(w_buf + k * 64 + hA);
        float4 w1 = *reinterpret_cast<const float4*>(w_buf + k * 64 + hB);
        const float a[8] = {a0.x, a0.y, a0.z, a0.w, a1.x, a1.y, a1.z, a1.w};
        #pragma unroll
        for (int i = 0; i < 8; i++) {
            accA[0][i] = fmaf(a[i], w0.x, accA[0][i]);
            accA[1][i] = fmaf(a[i], w0.y, accA[1][i]);
            accA[2][i] = fmaf(a[i], w0.z, accA[2][i]);
            accA[3][i] = fmaf(a[i], w0.w, accA[3][i]);
            accB[0][i] = fmaf(a[i], w1.x, accB[0][i]);
            accB[1][i] = fmaf(a[i], w1.y, accB[1][i]);
            accB[2][i] = fmaf(a[i], w1.z, accB[2][i]);
            accB[3][i] = fmaf(a[i], w1.w, accB[3][i]);
        }
    }

    // --- bias + relu ---
    #pragma unroll
    for (int c = 0; c < 4; c++) {
        float bA = bs[hA + c], bB = bs[hB + c];
        #pragma unroll
        for (int i = 0; i < 8; i++) {
            accA[c][i] = fmaxf(accA[c][i] + bA, 0.f);
            accB[c][i] = fmaxf(accB[c][i] + bB, 0.f);
        }
    }

    // --- write x_new to out ---
    #pragma unroll
    for (int i = 0; i < 8; i++) {
        int gn = base + n0 + i;
        if (gn < N) {
            float4 vA = make_float4(accA[0][i], accA[1][i], accA[2][i], accA[3][i]);
            float4 vB = make_float4(accB[0][i], accB[1][i], accB[2][i], accB[3][i]);
            *reinterpret_cast<float4*>(out + (long long)gn * 64 + hA) = vA;
            *reinterpret_cast<float4*>(out + (long long)gn * 64 + hB) = vB;
        }
    }
    __syncthreads();   // phase-1 reads of aT / w_buf done

    // --- restage: x_new transposed into aT (STS.128), Wp into w_buf ---
    #pragma unroll
    for (int c = 0; c < 4; c++) {
        *reinterpret_cast<float4*>(aT + (hA + c) * AS + n0) =
            make_float4(accA[c][0], accA[c][1], accA[c][2], accA[c][3]);
        *reinterpret_cast<float4*>(aT + (hA + c) * AS + n0 + 4) =
            make_float4(accA[c][4], accA[c][5], accA[c][6], accA[c][7]);
        *reinterpret_cast<float4*>(aT + (hB + c) * AS + n0) =
            make_float4(accB[c][0], accB[c][1], accB[c][2], accB[c][3]);
        *reinterpret_cast<float4*>(aT + (hB + c) * AS + n0 + 4) =
            make_float4(accB[c][4], accB[c][5], accB[c][6], accB[c][7]);
    }
    for (int i = t; i < 64 * 32; i += 256) w_buf[i] = Wp[i];
    __syncthreads();

    // --- head: y = x_new @ Wp + bp ; tile 8 nodes x 4 p ---
    const int p0 = tx * 4;
    float yacc[4][8];
    #pragma unroll
    for (int c = 0; c < 4; c++)
        #pragma unroll
        for (int i = 0; i < 8; i++) yacc[c][i] = 0.f;

    #pragma unroll 4
    for (int k = 0; k < 64; k++) {
        float4 a0 = *reinterpret_cast<const float4*>(aT + k * AS + n0);
        float4 a1 = *reinterpret_cast<const float4*>(aT + k * AS + n0 + 4);
        float4 wp = *reinterpret_cast<const float4*>(w_buf + k * 32 + p0);
        const float a[8] = {a0.x, a0.y, a0.z, a0.w, a1.x, a1.y, a1.z, a1.w};
        #pragma unroll
        for (int i = 0; i < 8; i++) {
            yacc[0][i] = fmaf(a[i], wp.x, yacc[0][i]);
            yacc[1][i] = fmaf(a[i], wp.y, yacc[1][i]);
            yacc[2][i] = fmaf(a[i], wp.z, yacc[2][i]);
            yacc[3][i] = fmaf(a[i], wp.w, yacc[3][i]);
        }
    }

    float* outy = out + (long long)N * 64;
    #pragma unroll
    for (int i = 0; i < 8; i++) {
        int gn = base + n0 + i;
        if (gn < N) {
            float4 r;
            r.x = yacc[0][i] + bps[p0 + 0];
            r.y = yacc[1][i] + bps[p0 + 1];
            r.z = yacc[2][i] + bps[p0 + 2];
            r.w = yacc[3][i] + bps[p0 + 3];
            *reinterpret_cast<float4*>(outy + (long long)gn * 32 + p0) = r;
        }
    }
}

// ---------------------------------------------------------------------------
extern "C" void kernel_launch(void* const* d_in, const int* in_sizes, int n_in,
                              void* d_out, int out_size)
{
    const float* x  = (const float*)d_in[0];
    const float* u  = (const float*)d_in[1];
    const void*  ei = d_in[2];
    const float* W  = (const float*)d_in[3];
    const float* B  = (const float*)d_in[4];
    const float* b  = (const float*)d_in[5];
    const float* Wp = (const float*)d_in[6];
    const float* bp = (const float*)d_in[7];
    float* out = (float*)d_out;

    int N = in_sizes[0] / 64;
    int E = in_sizes[2] / 2;

    const int smem_bytes = 21088 * 4;  // 84352
    cudaFuncSetAttribute(update_kernel,
                         cudaFuncAttributeMaxDynamicSharedMemorySize, smem_bytes);

    detect_idx_kernel<<<1, 32>>>(ei, E, N);

    long long nagg4 = ((long long)N * 64) / 4;
    int init_blocks = (int)((nagg4 + 255) / 256);
    init_kernel<<<init_blocks, 256>>>(nagg4, N);

    long long sc_threads = (long long)E * 16;
    int sc_blocks = (int)((sc_threads + 255) / 256);
    scatter_kernel<<<sc_blocks, 256>>>(x, ei, E);

    int up_blocks = (N + 255) / 256;
    update_kernel<<<up_blocks, 256, smem_bytes>>>(u, W, B, b, Wp, bp, out, N);
}